// round 1
// baseline (speedup 1.0000x reference)
#include <cuda_runtime.h>

// ---------------------------------------------------------------------------
// PPN on 3-level sparse voxel grid.
// inputs (metadata order):
//  0 feat1 [N1,80] f32   1 feat2 [N2,48]   2 feat3 [N3,16]
//  3 W1 [27,80,80]       4 W1s [27,80,2]   5 W2 [27,48,48]  6 W2s [27,48,2]
//  7 W3 [27,16,16]       8 W3p [27,16,3]   9 W3s [27,16,2] 10 W3t [27,16,5]
// 11 nbr1 [N1,27] i32   12 nbr2 [N2,27]   13 nbr3 [N3,27]
// 14 parent2 [N2] i32   15 parent3 [N3]
// 16 coords1 [N1,4] i32 17 coords2 [N2,4]
// output (flattened): points [N3,10] | ppn1 [N1,6] | ppn2 [N2,6] | mask1 [N1] | mask2 [N2]
// ---------------------------------------------------------------------------

#define N1_MAX 65536
#define N2_MAX 262144
#define N3_MAX 262144

__device__ float g_y1[(size_t)N1_MAX * 80];
__device__ float g_f2m[(size_t)N2_MAX * 48];
__device__ float g_y2[(size_t)N2_MAX * 48];
__device__ float g_f3m[(size_t)N3_MAX * 16];
__device__ float g_z[(size_t)N3_MAX * 16];

// ---------------------------------------------------------------------------
// Tiled submanifold conv: out[n,d] = sum_k sum_c feat[nbr[n,k],c] * W[k,c,d]
// Per k: stage W[k] transposed into smem ([d][c], padded) + gathered feature
// tile, then register-microtiled FFMA with float4 shared loads.
// ---------------------------------------------------------------------------
template <int CIN, int COUT, int TN, int RN, int RD>
__global__ void subconv_tile(const float* __restrict__ feat,
                             const int* __restrict__ nbr,
                             const float* __restrict__ W,
                             float* __restrict__ out, int N) {
    constexpr int CINP = CIN + 4;           // pad to break bank conflicts
    constexpr int NTX = COUT / RD;
    constexpr int NTY = TN / RN;
    static_assert(NTX * NTY == 256, "block must be 256 threads");
    static_assert(CIN % 4 == 0, "");

    extern __shared__ float sh[];
    float* sWt = sh;                        // [COUT][CINP]
    float* sF = sh + COUT * CINP;           // [TN][CINP]
    __shared__ int sIdx[TN];

    const int tid = threadIdx.x;
    const int tx = tid % NTX, ty = tid / NTX;
    const int n0 = blockIdx.x * TN;
    const int nb = ty * RN, db = tx * RD;

    float acc[RN][RD];
#pragma unroll
    for (int i = 0; i < RN; ++i)
#pragma unroll
        for (int j = 0; j < RD; ++j) acc[i][j] = 0.f;

    for (int k = 0; k < 27; ++k) {
        if (tid < TN) {
            int n = n0 + tid;
            sIdx[tid] = (n < N) ? nbr[n * 27 + k] : N;
        }
        const float* Wk = W + k * CIN * COUT;
        for (int i = tid; i < CIN * COUT; i += 256) {
            int c = i / COUT, d = i - c * COUT;
            sWt[d * CINP + c] = Wk[i];
        }
        __syncthreads();

        constexpr int VEC = CIN / 4;
        for (int i = tid; i < TN * VEC; i += 256) {
            int n = i / VEC, c4 = (i - n * VEC) * 4;
            int idx = sIdx[n];
            float4 v = make_float4(0.f, 0.f, 0.f, 0.f);
            if ((unsigned)idx < (unsigned)N)
                v = *reinterpret_cast<const float4*>(feat + (size_t)idx * CIN + c4);
            *reinterpret_cast<float4*>(sF + n * CINP + c4) = v;
        }
        __syncthreads();

#pragma unroll
        for (int c4 = 0; c4 < CIN; c4 += 4) {
            float4 a[RN], b[RD];
#pragma unroll
            for (int i = 0; i < RN; ++i)
                a[i] = *reinterpret_cast<const float4*>(sF + (nb + i) * CINP + c4);
#pragma unroll
            for (int j = 0; j < RD; ++j)
                b[j] = *reinterpret_cast<const float4*>(sWt + (db + j) * CINP + c4);
#pragma unroll
            for (int i = 0; i < RN; ++i)
#pragma unroll
                for (int j = 0; j < RD; ++j) {
                    acc[i][j] = fmaf(a[i].x, b[j].x, acc[i][j]);
                    acc[i][j] = fmaf(a[i].y, b[j].y, acc[i][j]);
                    acc[i][j] = fmaf(a[i].z, b[j].z, acc[i][j]);
                    acc[i][j] = fmaf(a[i].w, b[j].w, acc[i][j]);
                }
        }
        __syncthreads();
    }

#pragma unroll
    for (int i = 0; i < RN; ++i) {
        int n = n0 + nb + i;
        if (n < N) {
#pragma unroll
            for (int j = 0; j < RD; ++j)
                out[(size_t)n * COUT + db + j] = acc[i][j];
        }
    }
}

// ---------------------------------------------------------------------------
// Score head (Cout=2) + ppn concat (coords|scores) + softmax-threshold mask.
// softmax([s0,s1])[1] > 0.8  <=>  1/(1+exp(s0-s1)) > 0.8
// ---------------------------------------------------------------------------
template <int CIN>
__global__ void score_ppn_mask(const float* __restrict__ feat,
                               const int* __restrict__ nbr,
                               const float* __restrict__ Ws,
                               const int* __restrict__ coords,
                               float* __restrict__ ppn,
                               float* __restrict__ mask, int N) {
    __shared__ float sW[27 * 2 * CIN];  // [k][d][c]
    for (int i = threadIdx.x; i < 27 * CIN * 2; i += blockDim.x) {
        int k = i / (CIN * 2);
        int r = i - k * CIN * 2;
        int c = r >> 1, d = r & 1;
        sW[(k * 2 + d) * CIN + c] = Ws[i];
    }
    __syncthreads();
    int n = blockIdx.x * blockDim.x + threadIdx.x;
    if (n >= N) return;

    float a0 = 0.f, a1 = 0.f;
    for (int k = 0; k < 27; ++k) {
        int idx = nbr[n * 27 + k];
        if ((unsigned)idx < (unsigned)N) {
            const float4* fr = reinterpret_cast<const float4*>(feat + (size_t)idx * CIN);
            const float4* w0 = reinterpret_cast<const float4*>(sW + (k * 2 + 0) * CIN);
            const float4* w1 = reinterpret_cast<const float4*>(sW + (k * 2 + 1) * CIN);
#pragma unroll
            for (int j = 0; j < CIN / 4; ++j) {
                float4 v = fr[j], x = w0[j], y = w1[j];
                a0 += v.x * x.x + v.y * x.y + v.z * x.z + v.w * x.w;
                a1 += v.x * y.x + v.y * y.y + v.z * y.z + v.w * y.w;
            }
        }
    }
    ppn[(size_t)n * 6 + 0] = (float)coords[n * 4 + 0];
    ppn[(size_t)n * 6 + 1] = (float)coords[n * 4 + 1];
    ppn[(size_t)n * 6 + 2] = (float)coords[n * 4 + 2];
    ppn[(size_t)n * 6 + 3] = (float)coords[n * 4 + 3];
    ppn[(size_t)n * 6 + 4] = a0;
    ppn[(size_t)n * 6 + 5] = a1;
    float p = 1.f / (1.f + expf(a0 - a1));
    mask[n] = (p > 0.8f) ? 1.f : 0.f;
}

// featm[j,:] = feat[j,:] * mask[parent[j]]   (float4-vectorized)
template <int C>
__global__ void apply_att(const float* __restrict__ feat,
                          const int* __restrict__ parent,
                          const float* __restrict__ mask,
                          float* __restrict__ outF, int N) {
    int i = blockIdx.x * blockDim.x + threadIdx.x;  // over N*C/4
    int total = N * (C / 4);
    if (i >= total) return;
    int n = i / (C / 4);
    float m = mask[parent[n]];
    float4 v = reinterpret_cast<const float4*>(feat)[i];
    v.x *= m; v.y *= m; v.z *= m; v.w *= m;
    reinterpret_cast<float4*>(outF)[i] = v;
}

// Fine heads: points[n, 0:3|3:5|5:10] = subconv(z) with W3p/W3s/W3t fused.
__global__ void heads_kernel(const float* __restrict__ z,
                             const int* __restrict__ nbr,
                             const float* __restrict__ Wp,
                             const float* __restrict__ Wsc,
                             const float* __restrict__ Wt,
                             float* __restrict__ points, int N) {
    __shared__ float sW[27 * 10 * 16];  // [k][d][c]
    for (int i = threadIdx.x; i < 27 * 16 * 3; i += blockDim.x) {
        int k = i / 48; int r = i - k * 48; int c = r / 3; int d = r - c * 3;
        sW[(k * 10 + d) * 16 + c] = Wp[i];
    }
    for (int i = threadIdx.x; i < 27 * 16 * 2; i += blockDim.x) {
        int k = i / 32; int r = i - k * 32; int c = r >> 1; int d = r & 1;
        sW[(k * 10 + 3 + d) * 16 + c] = Wsc[i];
    }
    for (int i = threadIdx.x; i < 27 * 16 * 5; i += blockDim.x) {
        int k = i / 80; int r = i - k * 80; int c = r / 5; int d = r - c * 5;
        sW[(k * 10 + 5 + d) * 16 + c] = Wt[i];
    }
    __syncthreads();
    int n = blockIdx.x * blockDim.x + threadIdx.x;
    if (n >= N) return;

    float acc[10];
#pragma unroll
    for (int d = 0; d < 10; ++d) acc[d] = 0.f;

    for (int k = 0; k < 27; ++k) {
        int idx = nbr[n * 27 + k];
        if ((unsigned)idx < (unsigned)N) {
            const float4* zr = reinterpret_cast<const float4*>(z + (size_t)idx * 16);
            float4 v0 = zr[0], v1 = zr[1], v2 = zr[2], v3 = zr[3];
#pragma unroll
            for (int d = 0; d < 10; ++d) {
                const float4* wr = reinterpret_cast<const float4*>(sW + (k * 10 + d) * 16);
                float4 w0 = wr[0], w1 = wr[1], w2 = wr[2], w3 = wr[3];
                acc[d] += v0.x * w0.x + v0.y * w0.y + v0.z * w0.z + v0.w * w0.w
                        + v1.x * w1.x + v1.y * w1.y + v1.z * w1.z + v1.w * w1.w
                        + v2.x * w2.x + v2.y * w2.y + v2.z * w2.z + v2.w * w2.w
                        + v3.x * w3.x + v3.y * w3.y + v3.z * w3.z + v3.w * w3.w;
            }
        }
    }
#pragma unroll
    for (int d = 0; d < 10; ++d) points[(size_t)n * 10 + d] = acc[d];
}

// ---------------------------------------------------------------------------
extern "C" void kernel_launch(void* const* d_in, const int* in_sizes, int n_in,
                              void* d_out, int out_size) {
    const float* feat1 = (const float*)d_in[0];
    const float* feat2 = (const float*)d_in[1];
    const float* feat3 = (const float*)d_in[2];
    const float* W1  = (const float*)d_in[3];
    const float* W1s = (const float*)d_in[4];
    const float* W2  = (const float*)d_in[5];
    const float* W2s = (const float*)d_in[6];
    const float* W3  = (const float*)d_in[7];
    const float* W3p = (const float*)d_in[8];
    const float* W3s = (const float*)d_in[9];
    const float* W3t = (const float*)d_in[10];
    const int* nbr1 = (const int*)d_in[11];
    const int* nbr2 = (const int*)d_in[12];
    const int* nbr3 = (const int*)d_in[13];
    const int* parent2 = (const int*)d_in[14];
    const int* parent3 = (const int*)d_in[15];
    const int* coords1 = (const int*)d_in[16];
    const int* coords2 = (const int*)d_in[17];

    const int N1 = in_sizes[0] / 80;
    const int N2 = in_sizes[1] / 48;
    const int N3 = in_sizes[2] / 16;

    float* out = (float*)d_out;
    float* points = out;                                 // [N3,10]
    float* ppn1  = points + (size_t)N3 * 10;             // [N1,6]
    float* ppn2  = ppn1 + (size_t)N1 * 6;                // [N2,6]
    float* mask1 = ppn2 + (size_t)N2 * 6;                // [N1]
    float* mask2 = mask1 + N1;                           // [N2]

    float *y1, *f2m, *y2, *f3m, *z;
    cudaGetSymbolAddress((void**)&y1, g_y1);
    cudaGetSymbolAddress((void**)&f2m, g_f2m);
    cudaGetSymbolAddress((void**)&y2, g_y2);
    cudaGetSymbolAddress((void**)&f3m, g_f3m);
    cudaGetSymbolAddress((void**)&z, g_z);

    // --- Level 1 (coarse, 80ch) ---
    subconv_tile<80, 80, 64, 4, 5>
        <<<(N1 + 63) / 64, 256, (80 + 64) * 84 * sizeof(float)>>>(feat1, nbr1, W1, y1, N1);
    score_ppn_mask<80><<<(N1 + 255) / 256, 256>>>(y1, nbr1, W1s, coords1, ppn1, mask1, N1);

    // --- Level 2 (mid, 48ch) ---
    apply_att<48><<<(N2 * 12 + 255) / 256, 256>>>(feat2, parent2, mask1, f2m, N2);
    subconv_tile<48, 48, 64, 4, 3>
        <<<(N2 + 63) / 64, 256, (48 + 64) * 52 * sizeof(float)>>>(f2m, nbr2, W2, y2, N2);
    score_ppn_mask<48><<<(N2 + 255) / 256, 256>>>(y2, nbr2, W2s, coords2, ppn2, mask2, N2);

    // --- Level 3 (fine, 16ch) ---
    apply_att<16><<<(N3 * 4 + 255) / 256, 256>>>(feat3, parent3, mask2, f3m, N3);
    subconv_tile<16, 16, 128, 4, 2>
        <<<(N3 + 127) / 128, 256, (16 + 128) * 20 * sizeof(float)>>>(f3m, nbr3, W3, z, N3);
    heads_kernel<<<(N3 + 255) / 256, 256>>>(z, nbr3, W3p, W3s, W3t, points, N3);
}